// round 10
// baseline (speedup 1.0000x reference)
#include <cuda_runtime.h>
#include <cuda_bf16.h>
#include <cstdint>

#define NN 50000
#define NE 800000
#define KF 128      // IN_FEAT
#define NH 4        // heads
#define FD 16       // out feat per head
#define HF 64       // NH*FD
#define NEG 0.2f

// Scratch (device globals: allocation-free).
__device__ float4 g_h[NN * 16];    // h[n][64] as 16 float4 per node
__device__ float4 g_es[NN];        // e_src per node, 4 heads
__device__ float4 g_ed[NN];        // e_dst per node, 4 heads
__device__ int    g_is64;          // 1 if edge_index is int64, else 0 (int32)
__device__ int    g_deg[NN];       // per-dst degree
__device__ int    g_cur[NN];       // scatter cursors
__device__ int    g_rowptr[NN + 1];
__device__ int    g_srcs[NE];      // src ids sorted by dst

// ---------------------------------------------------------------------------
// K0: zero degree + cursor arrays.
// ---------------------------------------------------------------------------
__global__ void zero_kernel()
{
    const int i = blockIdx.x * 1024 + threadIdx.x;
    if (i < NN) { g_deg[i] = 0; g_cur[i] = 0; }
}

// ---------------------------------------------------------------------------
// K1 (fused): dtype probe (per-block local) + dst histogram + h=x@W + logits.
// ---------------------------------------------------------------------------
__global__ void __launch_bounds__(256) gemm_logits_hist_kernel(
    const float* __restrict__ x,
    const float* __restrict__ W,
    const float* __restrict__ a,
    const void* __restrict__ ei_raw)
{
    const int tid = threadIdx.x;

    // ---- per-block dtype probe (first 1024 entries interpreted as int64) ----
    __shared__ int s_is64;
    {
        const long long* e64 = (const long long*)ei_raw;
        bool ok = true;
        #pragma unroll
        for (int i = 0; i < 4; i++) {
            long long v = e64[tid * 4 + i];
            if (v < 0 || v >= NN) ok = false;
        }
        if (tid == 0) s_is64 = 1;
        __syncthreads();
        if (!ok) atomicAnd(&s_is64, 0);
        __syncthreads();
        if (blockIdx.x == 0 && tid == 0) g_is64 = s_is64;  // for scatter kernel
    }
    const int is64 = s_is64;

    // ---- dst-degree histogram (grid-stride over edges) ----
    {
        const int nth = gridDim.x * 256;
        if (is64) {
            const long long* e64 = (const long long*)ei_raw;
            for (int e = blockIdx.x * 256 + tid; e < NE; e += nth)
                atomicAdd(&g_deg[(int)e64[NE + e]], 1);
        } else {
            const int* e32 = (const int*)ei_raw;
            for (int e = blockIdx.x * 256 + tid; e < NE; e += nth)
                atomicAdd(&g_deg[e32[NE + e]], 1);
        }
    }

    // ---- stage W in shared ----
    __shared__ float2 Ws[KF * 32];           // 32 KB; lane j owns cols 2j,2j+1
    __shared__ float4 xs[8][4][KF / 4];      // 16 KB; 4 x-rows per warp

    const float2* W2 = reinterpret_cast<const float2*>(W);
    for (int i = tid; i < KF * 32; i += 256) Ws[i] = W2[i];
    __syncthreads();

    const int lane = tid & 31;
    const int w    = tid >> 5;
    const int head = lane >> 3;
    const int f0   = (2 * lane) & 15;

    const float as0 = a[head * 32 + f0];
    const float as1 = a[head * 32 + f0 + 1];
    const float ad0 = a[head * 32 + 16 + f0];
    const float ad1 = a[head * 32 + 17 + f0];

    const int ngroups = NN / 4;              // 12500 exactly
    const int nwarps  = gridDim.x * 8;

    for (int grp = blockIdx.x * 8 + w; grp < ngroups; grp += nwarps) {
        const int n0 = grp * 4;

        #pragma unroll
        for (int j = 0; j < 4; j++)
            xs[w][j][lane] = reinterpret_cast<const float4*>(x + (size_t)(n0 + j) * KF)[lane];
        __syncwarp();

        float ax0 = 0.f, ay0 = 0.f, ax1 = 0.f, ay1 = 0.f;
        float ax2 = 0.f, ay2 = 0.f, ax3 = 0.f, ay3 = 0.f;

        #pragma unroll
        for (int kk = 0; kk < KF / 4; kk++) {
            const float4 xv0 = xs[w][0][kk];
            const float4 xv1 = xs[w][1][kk];
            const float4 xv2 = xs[w][2][kk];
            const float4 xv3 = xs[w][3][kk];
            const float xk0[4] = {xv0.x, xv0.y, xv0.z, xv0.w};
            const float xk1[4] = {xv1.x, xv1.y, xv1.z, xv1.w};
            const float xk2[4] = {xv2.x, xv2.y, xv2.z, xv2.w};
            const float xk3[4] = {xv3.x, xv3.y, xv3.z, xv3.w};
            #pragma unroll
            for (int dk = 0; dk < 4; dk++) {
                const float2 wv = Ws[(kk * 4 + dk) * 32 + lane];
                ax0 = fmaf(xk0[dk], wv.x, ax0);  ay0 = fmaf(xk0[dk], wv.y, ay0);
                ax1 = fmaf(xk1[dk], wv.x, ax1);  ay1 = fmaf(xk1[dk], wv.y, ay1);
                ax2 = fmaf(xk2[dk], wv.x, ax2);  ay2 = fmaf(xk2[dk], wv.y, ay2);
                ax3 = fmaf(xk3[dk], wv.x, ax3);  ay3 = fmaf(xk3[dk], wv.y, ay3);
            }
        }

        float2* h2 = reinterpret_cast<float2*>(g_h);
        h2[(size_t)(n0 + 0) * 32 + lane] = make_float2(ax0, ay0);
        h2[(size_t)(n0 + 1) * 32 + lane] = make_float2(ax1, ay1);
        h2[(size_t)(n0 + 2) * 32 + lane] = make_float2(ax2, ay2);
        h2[(size_t)(n0 + 3) * 32 + lane] = make_float2(ax3, ay3);

        float psv[4], pdv[4];
        psv[0] = ax0 * as0 + ay0 * as1;  pdv[0] = ax0 * ad0 + ay0 * ad1;
        psv[1] = ax1 * as0 + ay1 * as1;  pdv[1] = ax1 * ad0 + ay1 * ad1;
        psv[2] = ax2 * as0 + ay2 * as1;  pdv[2] = ax2 * ad0 + ay2 * ad1;
        psv[3] = ax3 * as0 + ay3 * as1;  pdv[3] = ax3 * ad0 + ay3 * ad1;
        #pragma unroll
        for (int j = 0; j < 4; j++) {
            float ps = psv[j], pd = pdv[j];
            ps += __shfl_xor_sync(0xffffffffu, ps, 1);
            ps += __shfl_xor_sync(0xffffffffu, ps, 2);
            ps += __shfl_xor_sync(0xffffffffu, ps, 4);
            pd += __shfl_xor_sync(0xffffffffu, pd, 1);
            pd += __shfl_xor_sync(0xffffffffu, pd, 2);
            pd += __shfl_xor_sync(0xffffffffu, pd, 4);
            if ((lane & 7) == 0) {
                reinterpret_cast<float*>(g_es)[(n0 + j) * 4 + head] = ps;
                reinterpret_cast<float*>(g_ed)[(n0 + j) * 4 + head] = pd;
            }
        }
        __syncwarp();
    }
}

// ---------------------------------------------------------------------------
// K2: single-block exclusive scan of g_deg -> g_rowptr.  1024 threads, chunk 49.
// ---------------------------------------------------------------------------
__global__ void __launch_bounds__(1024) scan_kernel()
{
    __shared__ int part[1024];
    const int t = threadIdx.x;
    const int CH = (NN + 1023) / 1024;       // 49
    const int base = t * CH;

    int s = 0;
    for (int j = 0; j < CH; j++) {
        int idx = base + j;
        if (idx < NN) s += g_deg[idx];
    }
    part[t] = s;
    __syncthreads();

    // Hillis-Steele inclusive scan
    for (int off = 1; off < 1024; off <<= 1) {
        int v = (t >= off) ? part[t - off] : 0;
        __syncthreads();
        part[t] += v;
        __syncthreads();
    }

    int run = (t == 0) ? 0 : part[t - 1];    // exclusive prefix for this chunk
    for (int j = 0; j < CH; j++) {
        int idx = base + j;
        if (idx < NN) {
            g_rowptr[idx] = run;
            run += g_deg[idx];
        }
    }
    if (t == 1023) g_rowptr[NN] = run;       // = NE
}

// ---------------------------------------------------------------------------
// K3: scatter src ids into dst-sorted order.
// ---------------------------------------------------------------------------
__global__ void __launch_bounds__(256) scatter_kernel(const void* __restrict__ ei_raw)
{
    const int e = blockIdx.x * 256 + threadIdx.x;
    if (e >= NE) return;

    int src, dst;
    if (g_is64) {
        const long long* e64 = (const long long*)ei_raw;
        src = (int)e64[e];
        dst = (int)e64[NE + e];
    } else {
        const int* e32 = (const int*)ei_raw;
        src = e32[e];
        dst = e32[NE + e];
    }
    const int pos = g_rowptr[dst] + atomicAdd(&g_cur[dst], 1);
    g_srcs[pos] = src;
}

// ---------------------------------------------------------------------------
// K4: consumer — 16-lane group per dst node; register accumulation, one
// coalesced float4 store per lane. No atomics anywhere.
// ---------------------------------------------------------------------------
__global__ void __launch_bounds__(256) gather_kernel(float* __restrict__ out)
{
    const int tid = threadIdx.x;
    const int l   = tid & 15;                // lane owns cols [4l, 4l+4)
    const int dst = blockIdx.x * 16 + (tid >> 4);
    if (dst >= NN) return;

    const float4 ed = g_ed[dst];             // broadcast, hoisted
    const int beg = g_rowptr[dst];
    const int end = g_rowptr[dst + 1];
    const int h = l >> 2;                    // applied head

    float4 acc = make_float4(0.f, 0.f, 0.f, 0.f);

    int src_next = (beg < end) ? g_srcs[beg] : 0;
    for (int i = beg; i < end; i++) {
        const int src = src_next;
        src_next = (i + 1 < end) ? g_srcs[i + 1] : 0;

        const float4 es = g_es[src];
        const float4 hv = g_h[(size_t)src * 16 + l];

        float z0 = es.x + ed.x; z0 = z0 > 0.f ? z0 : NEG * z0;
        float z1 = es.y + ed.y; z1 = z1 > 0.f ? z1 : NEG * z1;
        float z2 = es.z + ed.z; z2 = z2 > 0.f ? z2 : NEG * z2;
        float z3 = es.w + ed.w; z3 = z3 > 0.f ? z3 : NEG * z3;
        const float m  = fmaxf(fmaxf(z0, z1), fmaxf(z2, z3));
        const float p0 = __expf(z0 - m);
        const float p1 = __expf(z1 - m);
        const float p2 = __expf(z2 - m);
        const float p3 = __expf(z3 - m);
        const float s  = p0 + p1 + p2 + p3;
        const float ph = (h == 0) ? p0 : (h == 1) ? p1 : (h == 2) ? p2 : p3;
        const float alpha = __fdividef(ph, s);

        acc.x = fmaf(alpha, hv.x, acc.x);
        acc.y = fmaf(alpha, hv.y, acc.y);
        acc.z = fmaf(alpha, hv.z, acc.z);
        acc.w = fmaf(alpha, hv.w, acc.w);
    }

    reinterpret_cast<float4*>(out)[(size_t)dst * 16 + l] = acc;
}

// ---------------------------------------------------------------------------
extern "C" void kernel_launch(void* const* d_in, const int* in_sizes, int n_in,
                              void* d_out, int out_size)
{
    const float* x  = (const float*)d_in[0];
    const void*  ei = (const void*)d_in[1];
    const float* W  = (const float*)d_in[2];
    const float* a  = (const float*)d_in[3];
    float* out = (float*)d_out;

    zero_kernel<<<(NN + 1023) / 1024, 1024>>>();
    gemm_logits_hist_kernel<<<592, 256>>>(x, W, a, ei);
    scan_kernel<<<1, 1024>>>();
    scatter_kernel<<<(NE + 255) / 256, 256>>>(ei);
    gather_kernel<<<(NN + 15) / 16, 256>>>(out);

    (void)in_sizes; (void)n_in; (void)out_size;
}

// round 13
// speedup vs baseline: 1.8039x; 1.8039x over previous
#include <cuda_runtime.h>
#include <cuda_bf16.h>
#include <cstdint>

#define NN 50000
#define NE 800000
#define KF 128      // IN_FEAT
#define NH 4        // heads
#define FD 16       // out feat per head
#define HF 64       // NH*FD
#define NEG 0.2f

// Scratch (device globals: allocation-free). float4 typing guarantees 16B alignment.
__device__ float4 g_h[NN * 16];   // h[n][64] as 16 float4 per node
__device__ float4 g_es[NN];       // e_src per node, 4 heads
__device__ float4 g_ed[NN];       // e_dst per node, 4 heads
__device__ int    g_is64;         // 1 if edge_index is int64, else 0 (int32)

// ---------------------------------------------------------------------------
// Kernel 1 (fused): out-zeroing + dtype probe + h = x@W + attention logits.
// ---------------------------------------------------------------------------
__global__ void __launch_bounds__(256) gemm_logits_kernel(
    const float* __restrict__ x,
    const float* __restrict__ W,
    const float* __restrict__ a,
    const void* __restrict__ ei_raw,
    float* __restrict__ out)
{
    const int tid = threadIdx.x;

    // ---- dtype probe (block 0 only; consumed by the NEXT kernel) ----
    if (blockIdx.x == 0) {
        const long long* e64 = (const long long*)ei_raw;
        bool ok = true;
        #pragma unroll
        for (int i = 0; i < 4; i++) {
            long long v = e64[tid * 4 + i];
            if (v < 0 || v >= NN) ok = false;
        }
        __shared__ int allok;
        if (tid == 0) allok = 1;
        __syncthreads();
        if (!ok) atomicAnd(&allok, 0);
        __syncthreads();
        if (tid == 0) g_is64 = allok;
    }

    // ---- zero the output (edge kernel reds into it; runs strictly after) ----
    {
        float4* o4 = reinterpret_cast<float4*>(out);
        const float4 z = make_float4(0.f, 0.f, 0.f, 0.f);
        for (int i = blockIdx.x * 256 + tid; i < NN * 16; i += gridDim.x * 256)
            o4[i] = z;
    }

    // ---- stage W in shared ----
    __shared__ float2 Ws[KF * 32];           // 32 KB; lane j owns cols 2j,2j+1
    __shared__ float4 xs[8][4][KF / 4];      // 16 KB; 4 x-rows per warp

    const float2* W2 = reinterpret_cast<const float2*>(W);
    for (int i = tid; i < KF * 32; i += 256) Ws[i] = W2[i];
    __syncthreads();

    const int lane = tid & 31;
    const int w    = tid >> 5;
    const int head = lane >> 3;              // cols 2*lane -> head = lane/8
    const int f0   = (2 * lane) & 15;

    const float as0 = a[head * 32 + f0];
    const float as1 = a[head * 32 + f0 + 1];
    const float ad0 = a[head * 32 + 16 + f0];
    const float ad1 = a[head * 32 + 17 + f0];

    const int ngroups = NN / 4;              // 12500 exactly
    const int nwarps  = gridDim.x * 8;

    for (int grp = blockIdx.x * 8 + w; grp < ngroups; grp += nwarps) {
        const int n0 = grp * 4;

        #pragma unroll
        for (int j = 0; j < 4; j++)
            xs[w][j][lane] = reinterpret_cast<const float4*>(x + (size_t)(n0 + j) * KF)[lane];
        __syncwarp();

        float ax0 = 0.f, ay0 = 0.f, ax1 = 0.f, ay1 = 0.f;
        float ax2 = 0.f, ay2 = 0.f, ax3 = 0.f, ay3 = 0.f;

        #pragma unroll
        for (int kk = 0; kk < KF / 4; kk++) {
            const float4 xv0 = xs[w][0][kk];
            const float4 xv1 = xs[w][1][kk];
            const float4 xv2 = xs[w][2][kk];
            const float4 xv3 = xs[w][3][kk];
            const float xk0[4] = {xv0.x, xv0.y, xv0.z, xv0.w};
            const float xk1[4] = {xv1.x, xv1.y, xv1.z, xv1.w};
            const float xk2[4] = {xv2.x, xv2.y, xv2.z, xv2.w};
            const float xk3[4] = {xv3.x, xv3.y, xv3.z, xv3.w};
            #pragma unroll
            for (int dk = 0; dk < 4; dk++) {
                const float2 wv = Ws[(kk * 4 + dk) * 32 + lane];
                ax0 = fmaf(xk0[dk], wv.x, ax0);  ay0 = fmaf(xk0[dk], wv.y, ay0);
                ax1 = fmaf(xk1[dk], wv.x, ax1);  ay1 = fmaf(xk1[dk], wv.y, ay1);
                ax2 = fmaf(xk2[dk], wv.x, ax2);  ay2 = fmaf(xk2[dk], wv.y, ay2);
                ax3 = fmaf(xk3[dk], wv.x, ax3);  ay3 = fmaf(xk3[dk], wv.y, ay3);
            }
        }

        float2* h2 = reinterpret_cast<float2*>(g_h);
        h2[(size_t)(n0 + 0) * 32 + lane] = make_float2(ax0, ay0);
        h2[(size_t)(n0 + 1) * 32 + lane] = make_float2(ax1, ay1);
        h2[(size_t)(n0 + 2) * 32 + lane] = make_float2(ax2, ay2);
        h2[(size_t)(n0 + 3) * 32 + lane] = make_float2(ax3, ay3);

        float psv[4], pdv[4];
        psv[0] = ax0 * as0 + ay0 * as1;  pdv[0] = ax0 * ad0 + ay0 * ad1;
        psv[1] = ax1 * as0 + ay1 * as1;  pdv[1] = ax1 * ad0 + ay1 * ad1;
        psv[2] = ax2 * as0 + ay2 * as1;  pdv[2] = ax2 * ad0 + ay2 * ad1;
        psv[3] = ax3 * as0 + ay3 * as1;  pdv[3] = ax3 * ad0 + ay3 * ad1;
        #pragma unroll
        for (int j = 0; j < 4; j++) {
            float ps = psv[j], pd = pdv[j];
            ps += __shfl_xor_sync(0xffffffffu, ps, 1);
            ps += __shfl_xor_sync(0xffffffffu, ps, 2);
            ps += __shfl_xor_sync(0xffffffffu, ps, 4);
            pd += __shfl_xor_sync(0xffffffffu, pd, 1);
            pd += __shfl_xor_sync(0xffffffffu, pd, 2);
            pd += __shfl_xor_sync(0xffffffffu, pd, 4);
            if ((lane & 7) == 0) {
                reinterpret_cast<float*>(g_es)[(n0 + j) * 4 + head] = ps;
                reinterpret_cast<float*>(g_ed)[(n0 + j) * 4 + head] = pd;
            }
        }
        __syncwarp();   // xs reused next iteration
    }
}

// ---------------------------------------------------------------------------
// Kernel 2: per-edge softmax-weighted gather + vectorized scatter-add.
// TWO edges per thread (e, e+NE/2) to double memory-level parallelism:
// all loads for both edges are independent and front-batched.
// 16 lanes per edge; lane l owns cols [4l,4l+4) -> applied head h=l>>2.
// Cooperative quad softmax (lane computes head j=l&3; shfl trees).
// ---------------------------------------------------------------------------
__device__ __forceinline__ void red_add_v4(float* p, float4 v) {
    asm volatile("red.global.add.v4.f32 [%0], {%1, %2, %3, %4};"
                 :: "l"(p), "f"(v.x), "f"(v.y), "f"(v.z), "f"(v.w)
                 : "memory");
}

#define NE_HALF (NE / 2)

__global__ void __launch_bounds__(256) edge_scatter_kernel(
    const void* __restrict__ ei_raw,
    float* __restrict__ out)
{
    const int gtid = blockIdx.x * 256 + threadIdx.x;
    const int g = gtid >> 4;
    if (g >= NE_HALF) return;
    const int l  = gtid & 15;         // lane within edge group
    const int wl = threadIdx.x & 31;  // lane within warp (for shfl indexing)

    const int e0 = g;
    const int e1 = g + NE_HALF;

    int src0, dst0, src1, dst1;
    if (g_is64) {
        const long long* e64 = (const long long*)ei_raw;
        src0 = (int)e64[e0];  dst0 = (int)e64[NE + e0];
        src1 = (int)e64[e1];  dst1 = (int)e64[NE + e1];
    } else {
        const int* e32 = (const int*)ei_raw;
        src0 = e32[e0];  dst0 = e32[NE + e0];
        src1 = e32[e1];  dst1 = e32[NE + e1];
    }

    const int j = l & 3;              // head this lane computes softmax term for
    const int h = l >> 2;             // head this lane applies to features

    const float* esf = reinterpret_cast<const float*>(g_es);
    const float* edf = reinterpret_cast<const float*>(g_ed);

    // independent logit loads for both edges (4 scalar LDGs in flight)
    const float es0 = esf[src0 * 4 + j];
    const float ed0 = edf[dst0 * 4 + j];
    const float es1 = esf[src1 * 4 + j];
    const float ed1 = edf[dst1 * 4 + j];

    // independent gathers for both edges (2 LDG.128 in flight)
    const float4 hv0 = g_h[(size_t)src0 * 16 + l];
    const float4 hv1 = g_h[(size_t)src1 * 16 + l];

    float z0 = es0 + ed0;  z0 = z0 > 0.f ? z0 : NEG * z0;
    float z1 = es1 + ed1;  z1 = z1 > 0.f ? z1 : NEG * z1;

    const unsigned m32 = 0xffffffffu;
    // interleaved quad max trees
    float mx0 = z0, mx1 = z1;
    mx0 = fmaxf(mx0, __shfl_xor_sync(m32, mx0, 1));
    mx1 = fmaxf(mx1, __shfl_xor_sync(m32, mx1, 1));
    mx0 = fmaxf(mx0, __shfl_xor_sync(m32, mx0, 2));
    mx1 = fmaxf(mx1, __shfl_xor_sync(m32, mx1, 2));
    const float p0 = __expf(z0 - mx0);
    const float p1 = __expf(z1 - mx1);
    float s0 = p0, s1 = p1;
    s0 += __shfl_xor_sync(m32, s0, 1);
    s1 += __shfl_xor_sync(m32, s1, 1);
    s0 += __shfl_xor_sync(m32, s0, 2);
    s1 += __shfl_xor_sync(m32, s1, 2);

    const int srclane = (wl & ~3) | h;
    const float ph0 = __shfl_sync(m32, p0, srclane);
    const float ph1 = __shfl_sync(m32, p1, srclane);
    const float a0 = ph0 / s0;
    const float a1 = ph1 / s1;

    float4 v0 = make_float4(a0 * hv0.x, a0 * hv0.y, a0 * hv0.z, a0 * hv0.w);
    float4 v1 = make_float4(a1 * hv1.x, a1 * hv1.y, a1 * hv1.z, a1 * hv1.w);

    red_add_v4(out + (size_t)dst0 * HF + 4 * l, v0);
    red_add_v4(out + (size_t)dst1 * HF + 4 * l, v1);
}

// ---------------------------------------------------------------------------
extern "C" void kernel_launch(void* const* d_in, const int* in_sizes, int n_in,
                              void* d_out, int out_size)
{
    const float* x  = (const float*)d_in[0];
    const void*  ei = (const void*)d_in[1];
    const float* W  = (const float*)d_in[2];
    const float* a  = (const float*)d_in[3];
    float* out = (float*)d_out;

    gemm_logits_kernel<<<592, 256>>>(x, W, a, ei, out);

    const int nthreads = NE_HALF * 16;
    edge_scatter_kernel<<<(nthreads + 255) / 256, 256>>>(ei, out);

    (void)in_sizes; (void)n_in; (void)out_size;
}